// round 5
// baseline (speedup 1.0000x reference)
#include <cuda_runtime.h>
#include <cstdint>

#define HG_L 16
#define HG_T (1u << 19)
#define HG_TMASK (HG_T - 1u)
#define WIDTH 64

#define P1 2654435761u
#define P2 805459861u
#define P3 3674653429u

// half-skewed smem row layout: 72 floats/row, half 1 at +36 floats
#define ROWP 72
#define HOFF 36

typedef unsigned long long u64;

// floor(16 * 1.5^l) for l = 0..15
__constant__ float c_res[HG_L] = {
    16.f, 24.f, 36.f, 54.f, 81.f, 121.f, 182.f, 273.f,
    410.f, 615.f, 922.f, 1383.f, 2075.f, 3113.f, 4670.f, 7006.f
};

// packed f32x2 fma (Blackwell FFMA2)
__device__ __forceinline__ u64 ffma2(u64 a, u64 b, u64 c) {
    u64 d;
    asm("fma.rn.f32x2 %0, %1, %2, %3;" : "=l"(d) : "l"(a), "l"(b), "l"(c));
    return d;
}
__device__ __forceinline__ u64 dup2(float x) {
    u64 d;
    asm("mov.b64 %0, {%1, %1};" : "=l"(d) : "f"(x));
    return d;
}

// Accumulate one level's (f0, f1) into this lane's 32-wide half of h1
// (16 packed f32x2) using W1 rows (row, row+1). Wp = row base + sub*HOFF.
__device__ __forceinline__ void acc_l1h(const float* __restrict__ Wp,
                                        float f0, float f1, u64* __restrict__ hp) {
    u64 F0 = dup2(f0), F1 = dup2(f1);
    const ulonglong2* w0 = (const ulonglong2*)(Wp);
    const ulonglong2* w1 = (const ulonglong2*)(Wp + ROWP);
#pragma unroll
    for (int j = 0; j < 8; j++) {
        ulonglong2 a = w0[j];
        ulonglong2 b = w1[j];
        hp[2 * j + 0] = ffma2(F0, a.x, ffma2(F1, b.x, hp[2 * j + 0]));
        hp[2 * j + 1] = ffma2(F0, a.y, ffma2(F1, b.y, hp[2 * j + 1]));
    }
}

// One x-corner pair (R3 scheme): if floor(x*r) even, both corners sit in one
// aligned float4; else two float2 gathers.
__device__ __forceinline__ void gather_pair(const float2* __restrict__ base,
                                            bool even, uint32_t ax0, uint32_t e,
                                            float vx0, float vx1, float wt,
                                            float& f0, float& f1) {
    if (even) {
        uint32_t id0 = (ax0 ^ e) & HG_TMASK;
        float4 q = __ldg((const float4*)base + (id0 >> 1));
        bool h = (id0 & 1u) != 0u;
        float wl = h ? vx1 : vx0;   // weight on q.xy
        float wh = h ? vx0 : vx1;   // weight on q.zw
        f0 = fmaf(wt, fmaf(wl, q.x, wh * q.z), f0);
        f1 = fmaf(wt, fmaf(wl, q.y, wh * q.w), f1);
    } else {
        float2 u = __ldg(base + ((ax0 ^ e) & HG_TMASK));
        float2 v = __ldg(base + (((ax0 + 1u) ^ e) & HG_TMASK));
        f0 = fmaf(wt, fmaf(vx0, u.x, vx1 * v.x), f0);
        f1 = fmaf(wt, fmaf(vx0, u.y, vx1 * v.y), f1);
    }
}

// 3D encode, lane-pair split on the z corner bit; same level in lockstep.
__device__ __forceinline__ void encode3(float x0, float x1, float x2,
                                        const float* __restrict__ tab,
                                        const float* __restrict__ W1s,
                                        int kbase, int sub, u64* __restrict__ hp) {
#pragma unroll 1
    for (int l = 0; l < HG_L; l++) {
        float r = c_res[l];
        float px = x0 * r, py = x1 * r, pz = x2 * r;
        float fx = floorf(px), fy = floorf(py), fz = floorf(pz);
        float wx = px - fx, wy = py - fy, wz = pz - fz;

        uint32_t ax0 = (uint32_t)fx;
        uint32_t ey[2];
        ey[0] = (uint32_t)fy * P1;  ey[1] = ey[0] + P1;
        uint32_t ezs = (uint32_t)fz * P2 + (sub ? P2 : 0u);
        float vx0 = 1.f - wx, vx1 = wx;
        float vy[2] = {1.f - wy, wy};
        float vzs = sub ? wz : (1.f - wz);

        const bool even = (ax0 & 1u) == 0u;
        const float2* base = (const float2*)tab + (size_t)l * HG_T;

        float f0 = 0.f, f1 = 0.f;
#pragma unroll
        for (int by = 0; by < 2; by++)
            gather_pair(base, even, ax0, ey[by] ^ ezs, vx0, vx1, vy[by] * vzs, f0, f1);

        f0 += __shfl_xor_sync(0xffffffffu, f0, 16);
        f1 += __shfl_xor_sync(0xffffffffu, f1, 16);
        acc_l1h(W1s + (size_t)(kbase + 2 * l) * ROWP + sub * HOFF, f0, f1, hp);
    }
}

// 4D encode, lane-pair split on the w corner bit.
__device__ __forceinline__ void encode4(float x0, float x1, float x2, float x3,
                                        const float* __restrict__ tab,
                                        const float* __restrict__ W1s,
                                        int kbase, int sub, u64* __restrict__ hp) {
#pragma unroll 1
    for (int l = 0; l < HG_L; l++) {
        float r = c_res[l];
        float px = x0 * r, py = x1 * r, pz = x2 * r, pw = x3 * r;
        float fx = floorf(px), fy = floorf(py), fz = floorf(pz), fw = floorf(pw);
        float wx = px - fx, wy = py - fy, wz = pz - fz, ww = pw - fw;

        uint32_t ax0 = (uint32_t)fx;
        uint32_t ey[2], ez[2];
        ey[0] = (uint32_t)fy * P1;  ey[1] = ey[0] + P1;
        ez[0] = (uint32_t)fz * P2;  ez[1] = ez[0] + P2;
        uint32_t ews = (uint32_t)fw * P3 + (sub ? P3 : 0u);
        float vx0 = 1.f - wx, vx1 = wx;
        float vy[2] = {1.f - wy, wy};
        float vz[2] = {1.f - wz, wz};
        float vws = sub ? ww : (1.f - ww);

        const bool even = (ax0 & 1u) == 0u;
        const float2* base = (const float2*)tab + (size_t)l * HG_T;

        float f0 = 0.f, f1 = 0.f;
#pragma unroll
        for (int c = 0; c < 4; c++) {
            const int by = c >> 1, bz = c & 1;
            gather_pair(base, even, ax0, ey[by] ^ ez[bz] ^ ews,
                        vx0, vx1, vy[by] * (vz[bz] * vws), f0, f1);
        }

        f0 += __shfl_xor_sync(0xffffffffu, f0, 16);
        f1 += __shfl_xor_sync(0xffffffffu, f1, 16);
        acc_l1h(W1s + (size_t)(kbase + 2 * l) * ROWP + sub * HOFF, f0, f1, hp);
    }
}

__global__ __launch_bounds__(256, 3)
void hashgrid_mlp_kernel(const float* __restrict__ fc,
                         const float* __restrict__ fn,
                         const float* __restrict__ pe,
                         const float* __restrict__ pos_tab,
                         const float* __restrict__ nrm_tab,
                         const float* __restrict__ pose_tab,
                         const float* __restrict__ W1,
                         const float* __restrict__ W2,
                         const float* __restrict__ W3,
                         float* __restrict__ out, int n) {
    __shared__ float W1s[96 * ROWP];    // 27.0 KB, half-skewed rows
    __shared__ float W2Ts[64 * ROWP];   // 18.0 KB, transposed + half-skewed
    __shared__ float W3s[64 * 9];       //  2.25 KB

    const int tid = threadIdx.x;
    for (int i = tid; i < 96 * 64; i += 256) {
        int row = i >> 6, col = i & 63;
        W1s[row * ROWP + (col >> 5) * HOFF + (col & 31)] = W1[i];
    }
    for (int i = tid; i < 64 * 64; i += 256) {
        int k = i >> 6, j = i & 63;          // W2[k][j]
        W2Ts[j * ROWP + (k >> 5) * HOFF + (k & 31)] = W2[i];
    }
    for (int i = tid; i < 64 * 9; i += 256) W3s[i] = W3[i];
    __syncthreads();

    const int warp = tid >> 5;
    const int lane = tid & 31;
    const int sub = lane >> 4;
    const int pt = lane & 15;
    const int pidx = blockIdx.x * 128 + warp * 16 + pt;
    const int pc = (pidx < n) ? pidx : (n - 1);   // clamp: all lanes active for shfl

    u64 hp[16];                  // this lane's 32-wide half of h1, packed f32x2
#pragma unroll
    for (int j = 0; j < 16; j++) hp[j] = 0ull;

    {
        float x0 = __ldg(fc + (size_t)pc * 3 + 0);
        float x1 = __ldg(fc + (size_t)pc * 3 + 1);
        float x2 = __ldg(fc + (size_t)pc * 3 + 2);
        encode3(x0, x1, x2, pos_tab, W1s, 0, sub, hp);
    }
    {
        float x0 = __ldg(fn + (size_t)pc * 3 + 0);
        float x1 = __ldg(fn + (size_t)pc * 3 + 1);
        float x2 = __ldg(fn + (size_t)pc * 3 + 2);
        encode3(x0, x1, x2, nrm_tab, W1s, 32, sub, hp);
    }
    {
        float x0 = __ldg(pe + (size_t)pc * 4 + 0);
        float x1 = __ldg(pe + (size_t)pc * 4 + 1);
        float x2 = __ldg(pe + (size_t)pc * 4 + 2);
        float x3 = __ldg(pe + (size_t)pc * 4 + 3);
        encode4(x0, x1, x2, x3, pose_tab, W1s, 64, sub, hp);
    }

    // unpack + relu (this lane's half)
    float h1[32];
#pragma unroll
    for (int j = 0; j < 16; j++) {
        float lo, hi;
        asm("mov.b64 {%0, %1}, %2;" : "=f"(lo), "=f"(hi) : "l"(hp[j]));
        h1[2 * j + 0] = fmaxf(lo, 0.f);
        h1[2 * j + 1] = fmaxf(hi, 0.f);
    }

    // layers 2 + 3, pair-split partial dots + shuffle combine
    float acc[9];
#pragma unroll
    for (int o = 0; o < 9; o++) acc[o] = 0.f;

#pragma unroll 2
    for (int j = 0; j < WIDTH; j++) {
        const float* wr = W2Ts + (size_t)j * ROWP + sub * HOFF;
        float s0 = 0.f, s1 = 0.f, s2 = 0.f, s3 = 0.f;
#pragma unroll
        for (int k = 0; k < 32; k += 4) {
            float4 a = *(const float4*)(wr + k);
            s0 = fmaf(h1[k + 0], a.x, s0);
            s1 = fmaf(h1[k + 1], a.y, s1);
            s2 = fmaf(h1[k + 2], a.z, s2);
            s3 = fmaf(h1[k + 3], a.w, s3);
        }
        float part = (s0 + s1) + (s2 + s3);
        float s = part + __shfl_xor_sync(0xffffffffu, part, 16);
        s = fmaxf(s, 0.f);
        const float* w3 = W3s + j * 9;
#pragma unroll
        for (int o = 0; o < 9; o++) acc[o] = fmaf(s, w3[o], acc[o]);
    }

    if (pidx < n) {
        float* op = out + (size_t)pidx * 9;
        if (sub == 0) {
            op[0] = acc[0]; op[1] = acc[1]; op[2] = acc[2]; op[3] = acc[3]; op[4] = acc[4];
        } else {
            op[5] = acc[5]; op[6] = acc[6]; op[7] = acc[7]; op[8] = acc[8];
        }
    }
}

extern "C" void kernel_launch(void* const* d_in, const int* in_sizes, int n_in,
                              void* d_out, int out_size) {
    const float* fc = (const float*)d_in[0];
    const float* fn = (const float*)d_in[1];
    const float* pe = (const float*)d_in[2];
    const float* pt = (const float*)d_in[3];
    const float* nt = (const float*)d_in[4];
    const float* qt = (const float*)d_in[5];
    const float* W1 = (const float*)d_in[6];
    const float* W2 = (const float*)d_in[7];
    const float* W3 = (const float*)d_in[8];
    float* out = (float*)d_out;

    const int n = in_sizes[0] / 3;
    const int blocks = (n + 127) / 128;   // 128 points per 256-thread block
    hashgrid_mlp_kernel<<<blocks, 256>>>(fc, fn, pe, pt, nt, qt, W1, W2, W3, out, n);
}